// round 5
// baseline (speedup 1.0000x reference)
#include <cuda_runtime.h>

#define BATCH   16
#define NPTS    4096
#define NB      128
#define THREADS 256
#define PPT     2
#define QPW     64                   // queries per warp (32 lanes x PPT)
#define GRIDX   (NPTS / (THREADS * PPT))   // 8
#define XMIN_F  (-6.0f)
#define XMAX_F  (6.0f)
#define WBUCK   ((XMAX_F - XMIN_F) / (float)NB)
#define BSCALE  ((float)NB / (XMAX_F - XMIN_F))

__device__ double g_acc[2];
__device__ float4 g_pts[2 * BATCH * NPTS];        // binned (x,y,z,||p||^2)
__device__ int    g_off[2 * BATCH * (NB + 1)];    // bucket prefix offsets

__global__ void zero_acc_kernel() {
    if (threadIdx.x < 2) g_acc[threadIdx.x] = 0.0;
}

// One block per (batch, set): histogram -> prefix -> scatter into bucket order.
__global__ __launch_bounds__(256) void bin_kernel(
    const float* __restrict__ xyz1, const float* __restrict__ xyz2)
{
    const int b = blockIdx.x, set = blockIdx.y;
    const float* __restrict__ src = ((set == 0) ? xyz1 : xyz2) + (size_t)b * NPTS * 3;
    __shared__ int cnt[NB];
    __shared__ int cur[NB + 1];
    const int tid = threadIdx.x;

    for (int k = tid; k < NB; k += 256) cnt[k] = 0;
    __syncthreads();
    for (int i = tid; i < NPTS; i += 256) {
        float x = src[3 * i];
        int bk = min(max((int)((x - XMIN_F) * BSCALE), 0), NB - 1);
        atomicAdd(&cnt[bk], 1);
    }
    __syncthreads();
    if (tid == 0) {
        int s = 0;
        for (int k = 0; k < NB; k++) { cur[k] = s; s += cnt[k]; }
        cur[NB] = s;
    }
    __syncthreads();
    int* off = g_off + (set * BATCH + b) * (NB + 1);
    for (int k = tid; k <= NB; k += 256) off[k] = cur[k];
    __syncthreads();
    float4* dst = g_pts + (set * BATCH + b) * NPTS;
    for (int i = tid; i < NPTS; i += 256) {
        float x = src[3 * i], y = src[3 * i + 1], z = src[3 * i + 2];
        int bk = min(max((int)((x - XMIN_F) * BSCALE), 0), NB - 1);
        int pos = atomicAdd(&cur[bk], 1);
        dst[pos] = make_float4(x, y, z, x * x + y * y + z * z);
    }
}

// Scan one candidate bucket: t = ||c||^2 - 2*(q . c)  (true dist = t + ||q||^2)
#define SCAN_BUCKET(J)                                                        \
    {                                                                         \
        int s_ = off[J], e_ = off[(J) + 1];                                   \
        _Pragma("unroll 4")                                                   \
        for (int i_ = s_; i_ < e_; i_++) {                                    \
            float4 cv = cp[i_];                                               \
            _Pragma("unroll")                                                 \
            for (int p_ = 0; p_ < PPT; p_++) {                                \
                float t_ = fmaf(qx[p_], cv.x,                                 \
                           fmaf(qy[p_], cv.y,                                 \
                           fmaf(qz[p_], cv.z, cv.w)));                        \
                mn[p_] = fminf(mn[p_], t_);                                   \
            }                                                                 \
        }                                                                     \
    }

__global__ __launch_bounds__(THREADS) void chamfer_kernel()
{
    const int dir = blockIdx.z;
    const int b   = blockIdx.y;
    const float4* __restrict__ qp  = g_pts + (dir * BATCH + b) * NPTS;
    const float4* __restrict__ cp  = g_pts + ((1 - dir) * BATCH + b) * NPTS;
    const int*    __restrict__ off = g_off + ((1 - dir) * BATCH + b) * (NB + 1);
    const int tid  = threadIdx.x;
    const int lane = tid & 31;
    const int warp = tid >> 5;
    // Region-swizzle: each block's 8 warps sample 8 spread query chunks.
    const int q0 = (warp * GRIDX + blockIdx.x) * QPW;

    float qx[PPT], qy[PPT], qz[PPT], qs[PPT], rx[PPT], mn[PPT];
#pragma unroll
    for (int p = 0; p < PPT; p++) {
        float4 v = qp[q0 + lane + 32 * p];
        rx[p] = v.x;
        qx[p] = -2.0f * v.x; qy[p] = -2.0f * v.y; qz[p] = -2.0f * v.z;
        qs[p] = v.w;
        mn[p] = 3.4e38f;
    }

    // Warp-median x -> center bucket; scan outward with conservative pruning.
    float xm = __shfl_sync(0xffffffffu, rx[0], 16);
    int jc = min(max((int)((xm - XMIN_F) * BSCALE), 0), NB - 1);

    SCAN_BUCKET(jc);

    bool ldone = false, rdone = false;
    for (int r = 1; r < NB; r++) {
        if (ldone && rdone) break;
        if (!ldone) {
            int j = jc - r;
            if (j < 0) ldone = true;
            else {
                float el = XMIN_F + j * WBUCK;
                float er = el + WBUCK;
                bool done = true;
#pragma unroll
                for (int p = 0; p < PPT; p++) {
                    // bucket 0 holds clamped outliers: left bound = -inf
                    float g = fmaxf(0.0f, fmaxf((j > 0) ? (el - rx[p]) : 0.0f,
                                                rx[p] - er));
                    done = done && (g * g >= mn[p] + qs[p]);
                }
                if (__all_sync(0xffffffffu, done)) ldone = true;
                else SCAN_BUCKET(j);
            }
        }
        if (!rdone) {
            int j = jc + r;
            if (j >= NB) rdone = true;
            else {
                float el = XMIN_F + j * WBUCK;
                float er = el + WBUCK;
                bool done = true;
#pragma unroll
                for (int p = 0; p < PPT; p++) {
                    // bucket NB-1 holds clamped outliers: right bound = +inf
                    float g = fmaxf(0.0f, fmaxf(el - rx[p],
                                                (j < NB - 1) ? (rx[p] - er) : 0.0f));
                    done = done && (g * g >= mn[p] + qs[p]);
                }
                if (__all_sync(0xffffffffu, done)) rdone = true;
                else SCAN_BUCKET(j);
            }
        }
    }

    // True min distance = mn + ||q||^2; sum and reduce.
    float s = 0.0f;
#pragma unroll
    for (int p = 0; p < PPT; p++) s += mn[p] + qs[p];

    __shared__ float red[THREADS / 32];
#pragma unroll
    for (int o = 16; o > 0; o >>= 1) s += __shfl_down_sync(0xffffffffu, s, o);
    if (lane == 0) red[warp] = s;
    __syncthreads();
    if (tid < THREADS / 32) {
        s = red[tid];
#pragma unroll
        for (int o = (THREADS / 64); o > 0; o >>= 1)
            s += __shfl_down_sync(0xffu, s, o);
        if (tid == 0) atomicAdd(&g_acc[dir], (double)s);
    }
}

__global__ void finalize_kernel(float* out) {
    if (threadIdx.x < 2)
        out[threadIdx.x] = (float)(g_acc[threadIdx.x] / (double)(BATCH * NPTS));
}

extern "C" void kernel_launch(void* const* d_in, const int* in_sizes, int n_in,
                              void* d_out, int out_size)
{
    const float* xyz1 = (const float*)d_in[0];
    const float* xyz2 = (const float*)d_in[1];
    float* out = (float*)d_out;

    zero_acc_kernel<<<1, 32>>>();
    bin_kernel<<<dim3(BATCH, 2), 256>>>(xyz1, xyz2);
    chamfer_kernel<<<dim3(GRIDX, BATCH, 2), THREADS>>>();   // (8,16,2) = 256 blocks
    finalize_kernel<<<1, 32>>>(out);
}